// round 1
// baseline (speedup 1.0000x reference)
#include <cuda_runtime.h>
#include <cuda_bf16.h>

// ============================================================================
// BlockG: StyleGAN2-ish synthesis block, fp32 baseline.
//   x   [8,512,32,32] -> up2 -> conv3x3(mod/demod) -> leaky -> conv3x3 -> leaky
//   rgb [8,3,32,32]   -> up2 -> + leaky(conv1x1(x2))
// Modulated conv rewritten as: scale input by style, shared-weight conv,
// scale output by demod factor.
// Output layout: d_out[0 : 8*512*64*64) = x, then d_out[... : +8*3*64*64) = rgb
// ============================================================================

#define B_ 8
#define C_ 512
#define HI 32
#define WI 32
#define HO 64
#define WO 64
#define PIX (HO*WO)           // 4096
#define XEL (B_*C_*PIX)       // 16777216
#define EPSV 1e-8f
#define SLOPE 0.2f

// ---------------- device scratch (static globals: allocation-free) ----------
__device__ float g_xup[XEL];          // up2(x) * s1
__device__ float g_y1 [XEL];          // leaky(conv1) * s2
__device__ float g_w1t[C_*9*C_];      // weight1 transposed [ci][tap][co]
__device__ float g_w2t[C_*9*C_];
__device__ float g_w2s1[C_*C_];       // sum_k w1^2 [co][ci]
__device__ float g_w2s2[C_*C_];
__device__ float g_s1[B_*C_], g_s2[B_*C_], g_s3[B_*C_];
__device__ float g_d1[B_*C_], g_d2[B_*C_];
__device__ float g_m3[B_*3*C_];       // w3*s3*d3

// ---------------- styles: s[b,i] = dot(w[b,:], A[i,:]) + bias[i] ------------
__global__ void k_styles(const float* __restrict__ w,
                         const float* __restrict__ A1, const float* __restrict__ b1,
                         const float* __restrict__ A2, const float* __restrict__ b2,
                         const float* __restrict__ A3, const float* __restrict__ b3)
{
    int gw = (blockIdx.x * blockDim.x + threadIdx.x) >> 5;   // global warp id
    int lane = threadIdx.x & 31;
    if (gw >= 3 * B_ * C_) return;
    int m = gw / (B_ * C_);
    int r = gw - m * (B_ * C_);
    int b = r >> 9, i = r & 511;
    const float* A  = (m == 0) ? A1 : (m == 1) ? A2 : A3;
    const float* bs = (m == 0) ? b1 : (m == 1) ? b2 : b3;
    float acc = 0.f;
    const float* wb = w + b * C_;
    const float* Ai = A + i * C_;
    for (int k = lane; k < C_; k += 32) acc += wb[k] * Ai[k];
    #pragma unroll
    for (int o = 16; o > 0; o >>= 1) acc += __shfl_xor_sync(0xffffffffu, acc, o);
    if (lane == 0) {
        float v = acc + bs[i];
        float* out = (m == 0) ? g_s1 : (m == 1) ? g_s2 : g_s3;
        out[b * C_ + i] = v;
    }
}

// ---------------- weight prep: sumsq + transpose ----------------------------
__global__ void k_wprep(const float* __restrict__ w1, const float* __restrict__ w2)
{
    int idx = blockIdx.x * blockDim.x + threadIdx.x;
    if (idx >= 2 * C_ * C_) return;
    int m = idx >> 18;
    int r = idx & (C_ * C_ - 1);
    int co = r >> 9, ci = r & 511;
    const float* w = m ? w2 : w1;
    float* wt  = m ? g_w2t  : g_w1t;
    float* w2s = m ? g_w2s2 : g_w2s1;
    const float* src = w + (size_t)(co * C_ + ci) * 9;
    float ss = 0.f;
    #pragma unroll
    for (int t = 0; t < 9; t++) {
        float v = src[t];
        ss += v * v;
        wt[(ci * 9 + t) * C_ + co] = v;
    }
    w2s[co * C_ + ci] = ss;
}

// ---------------- demod: d[b,co] = rsqrt(sum_ci w2s*s^2 + eps) --------------
__global__ void k_demod()
{
    int gw = (blockIdx.x * blockDim.x + threadIdx.x) >> 5;
    int lane = threadIdx.x & 31;
    if (gw >= 2 * B_ * C_) return;
    int m = gw >> 12;
    int r = gw & 4095;
    int b = r >> 9, co = r & 511;
    const float* w2s = m ? g_w2s2 : g_w2s1;
    const float* s   = m ? g_s2   : g_s1;
    float acc = 0.f;
    const float* wr = w2s + co * C_;
    const float* sr = s + b * C_;
    for (int ci = lane; ci < C_; ci += 32) { float sv = sr[ci]; acc += wr[ci] * sv * sv; }
    #pragma unroll
    for (int o = 16; o > 0; o >>= 1) acc += __shfl_xor_sync(0xffffffffu, acc, o);
    if (lane == 0) {
        float* d = m ? g_d2 : g_d1;
        d[b * C_ + co] = rsqrtf(acc + EPSV);
    }
}

// ---------------- toRGB modulation: m3 = w3*s3*d3 ---------------------------
__global__ void k_m3(const float* __restrict__ w3)
{
    int b = blockIdx.x / 3, j = blockIdx.x % 3;
    __shared__ float red[128];
    __shared__ float d3s;
    int tid = threadIdx.x;
    float acc = 0.f;
    for (int ci = tid; ci < C_; ci += 128) {
        float t = w3[j * C_ + ci] * g_s3[b * C_ + ci];
        acc += t * t;
    }
    red[tid] = acc; __syncthreads();
    for (int o = 64; o > 0; o >>= 1) { if (tid < o) red[tid] += red[tid + o]; __syncthreads(); }
    if (tid == 0) d3s = rsqrtf(red[0] + EPSV);
    __syncthreads();
    float d3 = d3s;
    for (int ci = tid; ci < C_; ci += 128)
        g_m3[(b * 3 + j) * C_ + ci] = w3[j * C_ + ci] * g_s3[b * C_ + ci] * d3;
}

// ---------------- upsample x2 (align_corners) + style scale -----------------
__device__ __forceinline__ float bilerp32(const float* __restrict__ p, int y, int x)
{
    const float F = 31.0f / 63.0f;
    float cy = (float)y * F, cx = (float)x * F;
    int iy0 = (int)cy, ix0 = (int)cx;
    float ty = cy - (float)iy0, tx = cx - (float)ix0;
    int iy1 = min(iy0 + 1, 31), ix1 = min(ix0 + 1, 31);
    float v00 = p[iy0 * 32 + ix0], v01 = p[iy0 * 32 + ix1];
    float v10 = p[iy1 * 32 + ix0], v11 = p[iy1 * 32 + ix1];
    // reference order: interpolate along H first, then W
    float a = v00 * (1.f - ty) + v10 * ty;
    float c = v01 * (1.f - ty) + v11 * ty;
    return a * (1.f - tx) + c * tx;
}

__global__ void k_upx(const float* __restrict__ xin)
{
    int idx = blockIdx.x * blockDim.x + threadIdx.x;
    if (idx >= XEL) return;
    int x = idx & 63;
    int y = (idx >> 6) & 63;
    int ci = (idx >> 12) & 511;
    int b = idx >> 21;
    const float* p = xin + (size_t)(b * C_ + ci) * (HI * WI);
    g_xup[idx] = bilerp32(p, y, x) * g_s1[b * C_ + ci];
}

// ---------------- 3x3 conv, shared weights across batch ---------------------
// block: 64 co x (16x16) pixels, 256 threads, per-thread 8co x 8px
__global__ void __launch_bounds__(256, 2)
k_conv3x3(int pass,
          const float* __restrict__ noise,
          const float* __restrict__ Bvec,
          float* __restrict__ dout)
{
    const float* in = pass ? g_y1  : g_xup;
    const float* wt = pass ? g_w2t : g_w1t;
    const float* dm = pass ? g_d2  : g_d1;
    float* out      = pass ? dout  : g_y1;

    int b = blockIdx.y;
    int cb = blockIdx.x >> 4;          // 0..7  (co block)
    int tile = blockIdx.x & 15;
    int ty0 = (tile >> 2) * 16, tx0 = (tile & 3) * 16;

    __shared__ float s_in[4][18 * 18];
    __shared__ float s_w[4][9][64];

    int tid = threadIdx.x;
    int tco = tid & 7;                 // 8 co groups
    int tpx = tid >> 3;                // 32 pixel groups
    int r  = tpx >> 1;                 // row in tile 0..15
    int c0 = (tpx & 1) * 8;            // col start

    float acc[8][8];
    #pragma unroll
    for (int j = 0; j < 8; j++)
        #pragma unroll
        for (int p = 0; p < 8; p++) acc[j][p] = 0.f;

    int co_base = cb * 64;
    const float* inB = in + (size_t)b * C_ * PIX;

    for (int ci0 = 0; ci0 < C_; ci0 += 4) {
        __syncthreads();
        // input tile with halo: 4 x 18 x 18
        for (int i = tid; i < 4 * 324; i += 256) {
            int cc = i / 324; int rem = i - cc * 324;
            int ly = rem / 18, lx = rem - ly * 18;
            int gy = ty0 - 1 + ly, gx = tx0 - 1 + lx;
            float v = 0.f;
            if (gy >= 0 && gy < 64 && gx >= 0 && gx < 64)
                v = inB[(ci0 + cc) * PIX + gy * 64 + gx];
            s_in[cc][ly * 18 + lx] = v;
        }
        // weights: 4 ci x 9 taps x 64 co (coalesced from transposed layout)
        for (int i = tid; i < 4 * 576; i += 256) {
            int cc = i / 576; int rem = i - cc * 576;
            int tap = rem >> 6; int col = rem & 63;
            s_w[cc][tap][col] = wt[((ci0 + cc) * 9 + tap) * C_ + co_base + col];
        }
        __syncthreads();

        #pragma unroll
        for (int cc = 0; cc < 4; cc++) {
            float rin[3][10];
            #pragma unroll
            for (int dy = 0; dy < 3; dy++)
                #pragma unroll
                for (int i = 0; i < 10; i++)
                    rin[dy][i] = s_in[cc][(r + dy) * 18 + c0 + i];
            #pragma unroll
            for (int j = 0; j < 8; j++) {
                const float* wp = &s_w[cc][0][tco * 8 + j];
                float w0 = wp[0],   w1 = wp[64],  w2 = wp[128];
                float w3 = wp[192], w4 = wp[256], w5 = wp[320];
                float w6 = wp[384], w7 = wp[448], w8 = wp[512];
                #pragma unroll
                for (int p = 0; p < 8; p++) {
                    float a = acc[j][p];
                    a = fmaf(w0, rin[0][p    ], a);
                    a = fmaf(w1, rin[0][p + 1], a);
                    a = fmaf(w2, rin[0][p + 2], a);
                    a = fmaf(w3, rin[1][p    ], a);
                    a = fmaf(w4, rin[1][p + 1], a);
                    a = fmaf(w5, rin[1][p + 2], a);
                    a = fmaf(w6, rin[2][p    ], a);
                    a = fmaf(w7, rin[2][p + 1], a);
                    a = fmaf(w8, rin[2][p + 2], a);
                    acc[j][p] = a;
                }
            }
        }
    }

    // epilogue: demod + noise + leaky (+ next style for pass 0)
    int y = ty0 + r;
    float nz[8];
    #pragma unroll
    for (int p = 0; p < 8; p++) nz[p] = noise[b * PIX + y * 64 + tx0 + c0 + p];

    #pragma unroll
    for (int j = 0; j < 8; j++) {
        int co = co_base + tco * 8 + j;
        float d  = dm[b * C_ + co];
        float bb = Bvec[co];
        float ps = pass ? 1.f : g_s2[b * C_ + co];
        float* orow = out + ((size_t)(b * C_ + co) * PIX) + y * 64 + tx0 + c0;
        #pragma unroll
        for (int p = 0; p < 8; p++) {
            float v = d * acc[j][p] + bb * nz[p];
            v = (v >= 0.f) ? v : SLOPE * v;
            orow[p] = v * ps;
        }
    }
}

// ---------------- toRGB 1x1 + rgb upsample + add ----------------------------
__global__ void k_final(const float* __restrict__ y2,      // d_out x region
                        const float* __restrict__ rgb_in,
                        const float* __restrict__ noise3,
                        const float* __restrict__ B3,
                        float* __restrict__ out_rgb)
{
    int b = blockIdx.y;
    int p = blockIdx.x * 256 + threadIdx.x;   // 0..4095
    __shared__ float s_m3[3 * C_];
    for (int i = threadIdx.x; i < 3 * C_; i += 256) s_m3[i] = g_m3[b * 3 * C_ + i];
    __syncthreads();

    int y = p >> 6, x = p & 63;
    const float* yb = y2 + (size_t)b * C_ * PIX + p;
    float a0 = 0.f, a1 = 0.f, a2 = 0.f;
    #pragma unroll 8
    for (int ci = 0; ci < C_; ci++) {
        float v = yb[(size_t)ci * PIX];
        a0 = fmaf(s_m3[ci], v, a0);
        a1 = fmaf(s_m3[C_ + ci], v, a1);
        a2 = fmaf(s_m3[2 * C_ + ci], v, a2);
    }
    float nz = noise3[b * PIX + p];
    float a[3] = {a0, a1, a2};
    #pragma unroll
    for (int j = 0; j < 3; j++) {
        float v = a[j] + B3[j] * nz;
        v = (v >= 0.f) ? v : SLOPE * v;
        const float* rp = rgb_in + (size_t)(b * 3 + j) * (HI * WI);
        out_rgb[(size_t)(b * 3 + j) * PIX + p] = bilerp32(rp, y, x) + v;
    }
}

// ---------------- launcher ---------------------------------------------------
extern "C" void kernel_launch(void* const* d_in, const int* in_sizes, int n_in,
                              void* d_out, int out_size)
{
    const float* x    = (const float*)d_in[0];
    const float* rgb  = (const float*)d_in[1];
    const float* w    = (const float*)d_in[2];
    const float* n1   = (const float*)d_in[3];
    const float* n2   = (const float*)d_in[4];
    const float* n3   = (const float*)d_in[5];
    const float* wt1  = (const float*)d_in[6];
    const float* A1w  = (const float*)d_in[7];
    const float* A1b  = (const float*)d_in[8];
    const float* B1   = (const float*)d_in[9];
    const float* wt2  = (const float*)d_in[10];
    const float* A2w  = (const float*)d_in[11];
    const float* A2b  = (const float*)d_in[12];
    const float* B2   = (const float*)d_in[13];
    const float* wt3  = (const float*)d_in[14];
    const float* A3w  = (const float*)d_in[15];
    const float* A3b  = (const float*)d_in[16];
    const float* B3   = (const float*)d_in[17];
    float* out = (float*)d_out;

    k_styles<<<(3 * B_ * C_ + 7) / 8, 256>>>(w, A1w, A1b, A2w, A2b, A3w, A3b);
    k_wprep <<<(2 * C_ * C_ + 255) / 256, 256>>>(wt1, wt2);
    k_demod <<<(2 * B_ * C_ + 7) / 8, 256>>>();
    k_m3    <<<B_ * 3, 128>>>(wt3);
    k_upx   <<<XEL / 256, 256>>>(x);
    k_conv3x3<<<dim3(128, B_), 256>>>(0, n1, B1, out);
    k_conv3x3<<<dim3(128, B_), 256>>>(1, n2, B2, out);
    k_final <<<dim3(PIX / 256, B_), 256>>>(out, rgb, n3, B3, out + (size_t)XEL);
}